// round 1
// baseline (speedup 1.0000x reference)
#include <cuda_runtime.h>

#define GN 100000
#define GE 800000
#define DD 128
#define BM 128
#define BK 32

// ---------------- scratch (device globals; no allocation allowed) ----------------
__device__ float g_y[GN * DD];      // x @ Wl  (to be aggregated)
__device__ float g_self[GN * DD];   // x @ Wr + b
__device__ float g_h0[GN * DD];     // layer outputs (ping)
__device__ float g_h1[GN * DD];     // layer outputs (pong)
__device__ int   g_rowptr[GN + 1];
__device__ int   g_cursor[GN];
__device__ int   g_esrc[GE];        // src ids sorted by dst (CSR)

// ---------------- CSR build ----------------
__global__ void zero_cnt_kernel() {
    int i = blockIdx.x * blockDim.x + threadIdx.x;
    if (i < GN) g_cursor[i] = 0;
}

__global__ void count_kernel(const int* __restrict__ dst) {
    int e = blockIdx.x * blockDim.x + threadIdx.x;
    if (e < GE) atomicAdd(&g_cursor[dst[e]], 1);
}

// single-block exclusive scan of g_cursor -> g_rowptr (and cursor = start offsets)
__global__ void scan_kernel() {
    __shared__ int wsum[32];
    __shared__ int carry_s;
    int t = threadIdx.x, lane = t & 31, w = t >> 5;
    if (t == 0) carry_s = 0;
    __syncthreads();
    for (int base = 0; base < GN; base += 1024) {
        int i = base + t;
        int v = (i < GN) ? g_cursor[i] : 0;
        int x = v;
        #pragma unroll
        for (int o = 1; o < 32; o <<= 1) {
            int u = __shfl_up_sync(0xffffffffu, x, o);
            if (lane >= o) x += u;
        }
        if (lane == 31) wsum[w] = x;
        __syncthreads();
        if (w == 0) {
            int s = wsum[lane];
            #pragma unroll
            for (int o = 1; o < 32; o <<= 1) {
                int u = __shfl_up_sync(0xffffffffu, s, o);
                if (lane >= o) s += u;
            }
            wsum[lane] = s;
        }
        __syncthreads();
        int off = carry_s + (w ? wsum[w - 1] : 0);
        int excl = off + x - v;
        if (i < GN) { g_rowptr[i] = excl; g_cursor[i] = excl; }
        int tot = wsum[31];
        __syncthreads();
        if (t == 0) carry_s += tot;
        __syncthreads();
        (void)tot;
    }
    if (t == 0) g_rowptr[GN] = carry_s;
}

__global__ void scatter_kernel(const int* __restrict__ src, const int* __restrict__ dst) {
    int e = blockIdx.x * blockDim.x + threadIdx.x;
    if (e < GE) {
        int p = atomicAdd(&g_cursor[dst[e]], 1);
        g_esrc[p] = src[e];
    }
}

// ---------------- fp32 SGEMM: C[M,128] = A[M,128] @ W[128,128] (+bias) ----------------
// a_sel: 0 = x (arg), 1 = g_h0, 2 = g_h1.  c_sel: 0 = g_y, 1 = g_self.
__global__ __launch_bounds__(256, 2) void gemm_kernel(
    const float* __restrict__ xin, const float* __restrict__ W,
    const float* __restrict__ bias, int a_sel, int c_sel)
{
    const float* A = (a_sel == 0) ? xin : (a_sel == 1 ? g_h0 : g_h1);
    float* C = (c_sel == 0) ? g_y : g_self;

    __shared__ float As[BK][BM + 4];   // transposed A tile [k][m], stride 132 keeps f4 align
    __shared__ float Bs[BK][DD];       // [k][n]

    const int tid = threadIdx.x;
    const int row0 = blockIdx.x * BM;
    const int ty = tid >> 4, tx = tid & 15;
    const int mBase = ty * 8, nBase = tx * 8;

    float acc[8][8];
    #pragma unroll
    for (int i = 0; i < 8; i++)
        #pragma unroll
        for (int j = 0; j < 8; j++) acc[i][j] = 0.f;

    #pragma unroll 1
    for (int kk = 0; kk < DD; kk += BK) {
        // A tile: BM x BK = 4096 floats = 1024 float4, 4 per thread, store transposed
        #pragma unroll
        for (int i = 0; i < 4; i++) {
            int id = tid + i * 256;       // 0..1023
            int m  = id >> 3;             // 8 float4 per row (BK=32)
            int kq = id & 7;
            int gr = row0 + m;
            float4 v = make_float4(0.f, 0.f, 0.f, 0.f);
            if (gr < GN) v = *(const float4*)&A[gr * DD + kk + kq * 4];
            As[kq * 4 + 0][m] = v.x;
            As[kq * 4 + 1][m] = v.y;
            As[kq * 4 + 2][m] = v.z;
            As[kq * 4 + 3][m] = v.w;
        }
        // B tile: BK x 128 = 4096 floats
        #pragma unroll
        for (int i = 0; i < 4; i++) {
            int id = tid + i * 256;
            int k  = id >> 5;
            int nq = id & 31;
            *(float4*)&Bs[k][nq * 4] = *(const float4*)&W[(kk + k) * DD + nq * 4];
        }
        __syncthreads();

        #pragma unroll
        for (int k = 0; k < BK; k++) {
            float a[8], b[8];
            *(float4*)&a[0] = *(const float4*)&As[k][mBase];
            *(float4*)&a[4] = *(const float4*)&As[k][mBase + 4];
            *(float4*)&b[0] = *(const float4*)&Bs[k][nBase];
            *(float4*)&b[4] = *(const float4*)&Bs[k][nBase + 4];
            #pragma unroll
            for (int i = 0; i < 8; i++)
                #pragma unroll
                for (int j = 0; j < 8; j++)
                    acc[i][j] += a[i] * b[j];
        }
        __syncthreads();
    }

    float bfrag[8];
    if (bias) {
        *(float4*)&bfrag[0] = *(const float4*)&bias[nBase];
        *(float4*)&bfrag[4] = *(const float4*)&bias[nBase + 4];
    } else {
        #pragma unroll
        for (int j = 0; j < 8; j++) bfrag[j] = 0.f;
    }

    #pragma unroll
    for (int i = 0; i < 8; i++) {
        int gr = row0 + mBase + i;
        if (gr < GN) {
            float4 o0, o1;
            o0.x = acc[i][0] + bfrag[0]; o0.y = acc[i][1] + bfrag[1];
            o0.z = acc[i][2] + bfrag[2]; o0.w = acc[i][3] + bfrag[3];
            o1.x = acc[i][4] + bfrag[4]; o1.y = acc[i][5] + bfrag[5];
            o1.z = acc[i][6] + bfrag[6]; o1.w = acc[i][7] + bfrag[7];
            *(float4*)&C[gr * DD + nBase]     = o0;
            *(float4*)&C[gr * DD + nBase + 4] = o1;
        }
    }
}

// ---------------- aggregation + self + LN + ReLU ----------------
// out_sel: 0 = g_h0, 1 = g_h1, 2 = out_arg
__global__ __launch_bounds__(128) void agg_kernel(
    const float* __restrict__ gamma, const float* __restrict__ beta,
    float* __restrict__ out_arg, int out_sel, int do_ln)
{
    float* out = (out_sel == 0) ? g_h0 : (out_sel == 1 ? g_h1 : out_arg);
    int node = blockIdx.x;
    int t = threadIdx.x;
    int beg = g_rowptr[node];
    int end = g_rowptr[node + 1];

    float a0 = 0.f, a1 = 0.f, a2 = 0.f, a3 = 0.f;
    int e = beg;
    for (; e + 4 <= end; e += 4) {
        int s0 = g_esrc[e], s1 = g_esrc[e + 1], s2 = g_esrc[e + 2], s3 = g_esrc[e + 3];
        a0 += g_y[s0 * DD + t];
        a1 += g_y[s1 * DD + t];
        a2 += g_y[s2 * DD + t];
        a3 += g_y[s3 * DD + t];
    }
    for (; e < end; e++) a0 += g_y[g_esrc[e] * DD + t];
    float acc = (a0 + a1) + (a2 + a3);

    float deg = (float)(end - beg);
    float v = acc / fmaxf(deg, 1.f) + g_self[node * DD + t];

    if (do_ln) {
        __shared__ float sh[8];
        float s1 = v, s2 = v * v;
        #pragma unroll
        for (int o = 16; o > 0; o >>= 1) {
            s1 += __shfl_xor_sync(0xffffffffu, s1, o);
            s2 += __shfl_xor_sync(0xffffffffu, s2, o);
        }
        int w = t >> 5;
        if ((t & 31) == 0) { sh[w] = s1; sh[4 + w] = s2; }
        __syncthreads();
        float t1 = sh[0] + sh[1] + sh[2] + sh[3];
        float t2 = sh[4] + sh[5] + sh[6] + sh[7];
        float mu  = t1 * (1.f / 128.f);
        float var = t2 * (1.f / 128.f) - mu * mu;
        v = (v - mu) * rsqrtf(var + 1e-5f) * gamma[t] + beta[t];
        v = fmaxf(v, 0.f);
    }
    out[node * DD + t] = v;
}

// ---------------- launch ----------------
extern "C" void kernel_launch(void* const* d_in, const int* in_sizes, int n_in,
                              void* d_out, int out_size)
{
    const float* x   = (const float*)d_in[0];
    const int*   src = (const int*)  d_in[1];
    const int*   dst = (const int*)  d_in[2];
    const float* Wl0 = (const float*)d_in[3];
    const float* Wr0 = (const float*)d_in[4];
    const float* b0  = (const float*)d_in[5];
    const float* Wl1 = (const float*)d_in[6];
    const float* Wr1 = (const float*)d_in[7];
    const float* b1  = (const float*)d_in[8];
    const float* Wl2 = (const float*)d_in[9];
    const float* Wr2 = (const float*)d_in[10];
    const float* b2  = (const float*)d_in[11];
    const float* g0  = (const float*)d_in[12];
    const float* be0 = (const float*)d_in[13];
    const float* g1  = (const float*)d_in[14];
    const float* be1 = (const float*)d_in[15];
    float* out = (float*)d_out;

    // CSR build (per launch; amortized over 3 layers)
    zero_cnt_kernel<<<(GN + 255) / 256, 256>>>();
    count_kernel<<<(GE + 255) / 256, 256>>>(dst);
    scan_kernel<<<1, 1024>>>();
    scatter_kernel<<<(GE + 255) / 256, 256>>>(src, dst);

    const int gb = (GN + BM - 1) / BM;

    // layer 0: in = x
    gemm_kernel<<<gb, 256>>>(x, Wl0, nullptr, 0, 0);
    gemm_kernel<<<gb, 256>>>(x, Wr0, b0,      0, 1);
    agg_kernel<<<GN, 128>>>(g0, be0, nullptr, 0, 1);   // -> g_h0

    // layer 1: in = g_h0
    gemm_kernel<<<gb, 256>>>(x, Wl1, nullptr, 1, 0);
    gemm_kernel<<<gb, 256>>>(x, Wr1, b1,      1, 1);
    agg_kernel<<<GN, 128>>>(g1, be1, nullptr, 1, 1);   // -> g_h1

    // layer 2: in = g_h1, no LN/ReLU, write d_out
    gemm_kernel<<<gb, 256>>>(x, Wl2, nullptr, 2, 0);
    gemm_kernel<<<gb, 256>>>(x, Wr2, b2,      2, 1);
    agg_kernel<<<GN, 128>>>(nullptr, nullptr, out, 2, 0);
}

// round 3
// speedup vs baseline: 1.3276x; 1.3276x over previous
#include <cuda_runtime.h>
#include <cuda_bf16.h>
#include <cstdint>

#define GN 100000
#define GE 800000
#define DD 128

// ---------------- scratch ----------------
__device__ float g_y[GN * DD];                 // agg-input  (h @ Wl)
__device__ float g_self[GN * DD];              // h @ Wr + b
__device__ __nv_bfloat16 g_Abf[GN * 256];      // [A_hi | A_lo] per row (K=256)
__device__ __nv_bfloat16 g_Bbf[3 * 384 * 256]; // per layer: rows [B_hi; B_hi; B_lo], cols [Wl | Wr]
__device__ int g_rowptr[GN + 1];
__device__ int g_cursor[GN];
__device__ int g_esrc[GE];

// ---------------- CSR build ----------------
__global__ void zero_cnt_kernel() {
    int i = blockIdx.x * blockDim.x + threadIdx.x;
    if (i < GN) g_cursor[i] = 0;
}

__global__ void count_kernel(const int* __restrict__ dst) {
    int e = blockIdx.x * blockDim.x + threadIdx.x;
    if (e < GE) atomicAdd(&g_cursor[dst[e]], 1);
}

__global__ void scan_kernel() {
    __shared__ int wsum[32];
    __shared__ int carry_s;
    int t = threadIdx.x, lane = t & 31, w = t >> 5;
    if (t == 0) carry_s = 0;
    __syncthreads();
    for (int base = 0; base < GN; base += 1024) {
        int i = base + t;
        int v = (i < GN) ? g_cursor[i] : 0;
        int x = v;
        #pragma unroll
        for (int o = 1; o < 32; o <<= 1) {
            int u = __shfl_up_sync(0xffffffffu, x, o);
            if (lane >= o) x += u;
        }
        if (lane == 31) wsum[w] = x;
        __syncthreads();
        if (w == 0) {
            int s = wsum[lane];
            #pragma unroll
            for (int o = 1; o < 32; o <<= 1) {
                int u = __shfl_up_sync(0xffffffffu, s, o);
                if (lane >= o) s += u;
            }
            wsum[lane] = s;
        }
        __syncthreads();
        int off = carry_s + (w ? wsum[w - 1] : 0);
        int excl = off + x - v;
        if (i < GN) { g_rowptr[i] = excl; g_cursor[i] = excl; }
        int tot = wsum[31];
        __syncthreads();
        if (t == 0) carry_s += tot;
        __syncthreads();
        (void)tot;
    }
    if (t == 0) g_rowptr[GN] = carry_s;
}

__global__ void scatter_kernel(const int* __restrict__ src, const int* __restrict__ dst) {
    int e = blockIdx.x * blockDim.x + threadIdx.x;
    if (e < GE) {
        int p = atomicAdd(&g_cursor[dst[e]], 1);
        g_esrc[p] = src[e];
    }
}

// ---------------- input conversion: x -> [hi|lo] bf16 ----------------
__global__ void convX_kernel(const float* __restrict__ x) {
    int i = blockIdx.x * blockDim.x + threadIdx.x;
    if (i < GN * DD) {
        float v = x[i];
        __nv_bfloat16 hi = __float2bfloat16_rn(v);
        __nv_bfloat16 lo = __float2bfloat16_rn(v - __bfloat162float(hi));
        int row = i >> 7, col = i & 127;
        g_Abf[row * 256 + col]       = hi;
        g_Abf[row * 256 + 128 + col] = lo;
    }
}

// ---------------- weight prep: g_Bbf[l] = rows [hi;hi;lo] of [Wl|Wr] ----------------
__global__ void prepB_kernel(const float* Wl0, const float* Wr0,
                             const float* Wl1, const float* Wr1,
                             const float* Wl2, const float* Wr2) {
    int r = blockIdx.x, l = blockIdx.y, n = threadIdx.x;
    const float* Wl = (l == 0) ? Wl0 : (l == 1 ? Wl1 : Wl2);
    const float* Wr = (l == 0) ? Wr0 : (l == 1 ? Wr1 : Wr2);
    const float* W = (n < 128) ? Wl : Wr;
    int col = n & 127;
    int k = (r < 128) ? r : (r < 256 ? r - 128 : r - 256);
    float v = W[k * 128 + col];
    __nv_bfloat16 hi = __float2bfloat16_rn(v);
    __nv_bfloat16 o = (r < 256) ? hi : __float2bfloat16_rn(v - __bfloat162float(hi));
    g_Bbf[(l * 384 + r) * 256 + n] = o;
}

// ---------------- tensor-core GEMM ----------------
// C[100000, 256] = A'[100000, K=384] @ B'[384, 256]  (bf16 in, fp32 accum)
// blockIdx.y = 0 -> cols 0-127 -> g_y ; 1 -> cols 128-255 -> g_self (+bias)
__device__ __forceinline__ void ldsm_x4(uint32_t& r0, uint32_t& r1, uint32_t& r2, uint32_t& r3, uint32_t a) {
    asm volatile("ldmatrix.sync.aligned.m8n8.x4.shared.b16 {%0,%1,%2,%3}, [%4];"
                 : "=r"(r0), "=r"(r1), "=r"(r2), "=r"(r3) : "r"(a));
}
__device__ __forceinline__ void ldsm_x4_t(uint32_t& r0, uint32_t& r1, uint32_t& r2, uint32_t& r3, uint32_t a) {
    asm volatile("ldmatrix.sync.aligned.m8n8.x4.trans.shared.b16 {%0,%1,%2,%3}, [%4];"
                 : "=r"(r0), "=r"(r1), "=r"(r2), "=r"(r3) : "r"(a));
}
__device__ __forceinline__ void mma16816(float* c, const uint32_t* a, const uint32_t* b) {
    asm volatile("mma.sync.aligned.m16n8k16.row.col.f32.bf16.bf16.f32 "
                 "{%0,%1,%2,%3}, {%4,%5,%6,%7}, {%8,%9}, {%0,%1,%2,%3};"
                 : "+f"(c[0]), "+f"(c[1]), "+f"(c[2]), "+f"(c[3])
                 : "r"(a[0]), "r"(a[1]), "r"(a[2]), "r"(a[3]), "r"(b[0]), "r"(b[1]));
}

__global__ __launch_bounds__(256) void gemm_bf16_kernel(int layer, const float* __restrict__ bias) {
    __shared__ __align__(16) __nv_bfloat16 As[128][72];   // 64 used + pad 8
    __shared__ __align__(16) __nv_bfloat16 Bs[64][136];   // 128 used + pad 8

    const int tid = threadIdx.x;
    const int wid = tid >> 5, lane = tid & 31;
    const int warpM = (wid & 3) * 32;       // 4 warps along M
    const int warpN = (wid >> 2) * 64;      // 2 warps along N
    const int row0 = blockIdx.x * 128;
    const int n0 = blockIdx.y * 128;        // 0 or 128 in B' columns
    const __nv_bfloat16* Bmat = g_Bbf + layer * 384 * 256;

    float acc[2][8][4];
    #pragma unroll
    for (int mi = 0; mi < 2; mi++)
        #pragma unroll
        for (int ni = 0; ni < 8; ni++)
            #pragma unroll
            for (int q = 0; q < 4; q++) acc[mi][ni][q] = 0.f;

    // ldsm base addresses (per-thread, constant across chunks)
    uint32_t aAddrBase[2], bAddrBase[4];
    #pragma unroll
    for (int mi = 0; mi < 2; mi++)
        aAddrBase[mi] = (uint32_t)__cvta_generic_to_shared(
            &As[warpM + mi * 16 + (lane & 15)][(lane >> 4) * 8]);
    #pragma unroll
    for (int p = 0; p < 4; p++)
        bAddrBase[p] = (uint32_t)__cvta_generic_to_shared(
            &Bs[(lane & 7) + (lane & 8)][warpN + p * 16 + (lane >> 4) * 8]);

    #pragma unroll 1
    for (int c = 0; c < 6; c++) {
        // A chunk: rows row0..+127, storage cols bc..bc+63 (chunks 4,5 reuse A_hi)
        const int bc = (c < 4) ? c * 64 : (c - 4) * 64;
        #pragma unroll
        for (int i = 0; i < 4; i++) {
            int id = tid + i * 256;
            int r = id >> 3, cq = id & 7;
            int gr = row0 + r;
            uint4 v = make_uint4(0u, 0u, 0u, 0u);
            if (gr < GN) v = *(const uint4*)&g_Abf[gr * 256 + bc + cq * 8];
            *(uint4*)&As[r][cq * 8] = v;
        }
        // B chunk: rows c*64..+63, cols n0..n0+127
        #pragma unroll
        for (int i = 0; i < 4; i++) {
            int id = tid + i * 256;
            int r = id >> 4, nq = id & 15;
            *(uint4*)&Bs[r][nq * 8] = *(const uint4*)&Bmat[(c * 64 + r) * 256 + n0 + nq * 8];
        }
        __syncthreads();

        #pragma unroll
        for (int ks = 0; ks < 4; ks++) {
            uint32_t a[2][4];
            #pragma unroll
            for (int mi = 0; mi < 2; mi++)
                ldsm_x4(a[mi][0], a[mi][1], a[mi][2], a[mi][3],
                        aAddrBase[mi] + ks * 16 * sizeof(__nv_bfloat16));
            uint32_t b[8][2];
            #pragma unroll
            for (int p = 0; p < 4; p++)
                ldsm_x4_t(b[2 * p][0], b[2 * p][1], b[2 * p + 1][0], b[2 * p + 1][1],
                          bAddrBase[p] + ks * 16 * 136 * sizeof(__nv_bfloat16));
            #pragma unroll
            for (int mi = 0; mi < 2; mi++)
                #pragma unroll
                for (int ni = 0; ni < 8; ni++)
                    mma16816(acc[mi][ni], a[mi], b[ni]);
        }
        __syncthreads();
    }

    // epilogue
    float* Cout = (blockIdx.y == 0) ? g_y : g_self;
    const int g = lane >> 2, tig = lane & 3;
    #pragma unroll
    for (int mi = 0; mi < 2; mi++) {
        #pragma unroll
        for (int ni = 0; ni < 8; ni++) {
            int col = warpN + ni * 8 + tig * 2;
            float b0 = 0.f, b1 = 0.f;
            if (blockIdx.y == 1) { b0 = bias[col]; b1 = bias[col + 1]; }
            int r1 = row0 + warpM + mi * 16 + g;
            int r2 = r1 + 8;
            if (r1 < GN) {
                float2 v = make_float2(acc[mi][ni][0] + b0, acc[mi][ni][1] + b1);
                *(float2*)&Cout[r1 * DD + col] = v;
            }
            if (r2 < GN) {
                float2 v = make_float2(acc[mi][ni][2] + b0, acc[mi][ni][3] + b1);
                *(float2*)&Cout[r2 * DD + col] = v;
            }
        }
    }
}

// ---------------- aggregation + self + LN + ReLU (+ bf16 hi/lo for next layer) ----------------
__global__ __launch_bounds__(128) void agg_kernel(
    const float* __restrict__ gamma, const float* __restrict__ beta,
    float* __restrict__ out_arg, int write_bf16, int do_ln)
{
    int node = blockIdx.x;
    int t = threadIdx.x;
    int beg = g_rowptr[node];
    int end = g_rowptr[node + 1];

    float a0 = 0.f, a1 = 0.f, a2 = 0.f, a3 = 0.f;
    int e = beg;
    for (; e + 4 <= end; e += 4) {
        int s0 = g_esrc[e], s1 = g_esrc[e + 1], s2 = g_esrc[e + 2], s3 = g_esrc[e + 3];
        a0 += g_y[s0 * DD + t];
        a1 += g_y[s1 * DD + t];
        a2 += g_y[s2 * DD + t];
        a3 += g_y[s3 * DD + t];
    }
    for (; e < end; e++) a0 += g_y[g_esrc[e] * DD + t];
    float acc = (a0 + a1) + (a2 + a3);

    float deg = (float)(end - beg);
    float v = acc / fmaxf(deg, 1.f) + g_self[node * DD + t];

    if (do_ln) {
        __shared__ float sh[8];
        float s1 = v, s2 = v * v;
        #pragma unroll
        for (int o = 16; o > 0; o >>= 1) {
            s1 += __shfl_xor_sync(0xffffffffu, s1, o);
            s2 += __shfl_xor_sync(0xffffffffu, s2, o);
        }
        int w = t >> 5;
        if ((t & 31) == 0) { sh[w] = s1; sh[4 + w] = s2; }
        __syncthreads();
        float t1 = sh[0] + sh[1] + sh[2] + sh[3];
        float t2 = sh[4] + sh[5] + sh[6] + sh[7];
        float mu  = t1 * (1.f / 128.f);
        float var = t2 * (1.f / 128.f) - mu * mu;
        v = (v - mu) * rsqrtf(var + 1e-5f) * gamma[t] + beta[t];
        v = fmaxf(v, 0.f);
    }

    if (write_bf16) {
        __nv_bfloat16 hi = __float2bfloat16_rn(v);
        __nv_bfloat16 lo = __float2bfloat16_rn(v - __bfloat162float(hi));
        g_Abf[node * 256 + t]       = hi;
        g_Abf[node * 256 + 128 + t] = lo;
    } else {
        out_arg[node * DD + t] = v;
    }
}

// ---------------- launch ----------------
extern "C" void kernel_launch(void* const* d_in, const int* in_sizes, int n_in,
                              void* d_out, int out_size)
{
    const float* x   = (const float*)d_in[0];
    const int*   src = (const int*)  d_in[1];
    const int*   dst = (const int*)  d_in[2];
    const float* Wl0 = (const float*)d_in[3];
    const float* Wr0 = (const float*)d_in[4];
    const float* b0  = (const float*)d_in[5];
    const float* Wl1 = (const float*)d_in[6];
    const float* Wr1 = (const float*)d_in[7];
    const float* b1  = (const float*)d_in[8];
    const float* Wl2 = (const float*)d_in[9];
    const float* Wr2 = (const float*)d_in[10];
    const float* b2  = (const float*)d_in[11];
    const float* g0  = (const float*)d_in[12];
    const float* be0 = (const float*)d_in[13];
    const float* g1  = (const float*)d_in[14];
    const float* be1 = (const float*)d_in[15];
    float* out = (float*)d_out;

    // CSR build
    zero_cnt_kernel<<<(GN + 255) / 256, 256>>>();
    count_kernel<<<(GE + 255) / 256, 256>>>(dst);
    scan_kernel<<<1, 1024>>>();
    scatter_kernel<<<(GE + 255) / 256, 256>>>(src, dst);

    // bf16 prep
    convX_kernel<<<(GN * DD + 255) / 256, 256>>>(x);
    prepB_kernel<<<dim3(384, 3), 256>>>(Wl0, Wr0, Wl1, Wr1, Wl2, Wr2);

    const dim3 gg((GN + 127) / 128, 2);

    // layer 0
    gemm_bf16_kernel<<<gg, 256>>>(0, b0);
    agg_kernel<<<GN, 128>>>(g0, be0, nullptr, 1, 1);
    // layer 1
    gemm_bf16_kernel<<<gg, 256>>>(1, b1);
    agg_kernel<<<GN, 128>>>(g1, be1, nullptr, 1, 1);
    // layer 2
    gemm_bf16_kernel<<<gg, 256>>>(2, b2);
    agg_kernel<<<GN, 128>>>(nullptr, nullptr, out, 0, 0);
}